// round 17
// baseline (speedup 1.0000x reference)
#include <cuda_runtime.h>
#include <cstdint>

#define BDIM 256
#define NROWS 4096
#define DCOLS 8192
#define CHUNK_FLOATS 1024                       // 4KB per tensor per stage
#define NCHUNKS (DCOLS / CHUNK_FLOATS)          // 8
#define NSTAGES 4

__device__ __forceinline__ float smoothl1(float a, float b) {
    float d = a - b;
    float ad = fabsf(d);
    return (ad < 1.0f) ? (0.5f * d * d) : (ad - 0.5f);
}

__device__ __forceinline__ uint32_t smem_u32(const void* p) {
    return (uint32_t)__cvta_generic_to_shared(p);
}

__device__ __forceinline__ void cp16(uint32_t dst, const void* src) {
    asm volatile("cp.async.cg.shared.global [%0], [%1], 16;"
                 :: "r"(dst), "l"(src) : "memory");
}

__device__ __forceinline__ void cp_commit() {
    asm volatile("cp.async.commit_group;" ::: "memory");
}

template <int N>
__device__ __forceinline__ void cp_wait() {
    asm volatile("cp.async.wait_group %0;" :: "n"(N) : "memory");
}

__global__ void zero_out_kernel(float* __restrict__ out) {
    out[0] = 0.0f;
}

__global__ __launch_bounds__(BDIM)
void mask_smoothl1_cpasync4_kernel(const float* __restrict__ in,
                                   const float* __restrict__ tgt,
                                   const int* __restrict__ mask,
                                   float* __restrict__ out) {
    // 4-stage pipeline: [stage][A(1024) | B(1024)], 8KB per stage.
    // Each thread writes AND reads only its own 16B slots -> thread-local
    // visibility via cp.async.wait_group; no mainloop barriers needed.
    __shared__ alignas(16) float buf[NSTAGES][2 * CHUNK_FLOATS];
    __shared__ float warp_sums[BDIM / 32];

    const int row = blockIdx.x;
    const int tid = threadIdx.x;
    const int wid = tid >> 5;
    const int lid = tid & 31;
    const int m = mask[row];

    if (m == 0) return;   // contributes nothing

    const float* __restrict__ A = in  + (size_t)row * DCOLS;
    const float* __restrict__ B = tgt + (size_t)row * DCOLS;

    uint32_t dA[NSTAGES], dB[NSTAGES];
    #pragma unroll
    for (int s = 0; s < NSTAGES; ++s) {
        dA[s] = smem_u32(&buf[s][tid * 4]);
        dB[s] = smem_u32(&buf[s][CHUNK_FLOATS + tid * 4]);
    }

    // prologue: issue chunks 0..2 (3 groups in flight)
    #pragma unroll
    for (int c = 0; c < NSTAGES - 1; ++c) {
        const int off = c * CHUNK_FLOATS + tid * 4;
        cp16(dA[c], A + off);
        cp16(dB[c], B + off);
        cp_commit();
    }

    float acc0 = 0.0f, acc1 = 0.0f;

    // STEP(c, WAITN): maybe-issue chunk c+3, wait until chunk c landed, consume
#define STEP(c, WAITN)                                                      \
    {                                                                       \
        if ((c) + NSTAGES - 1 < NCHUNKS) {                                  \
            const int nc  = (c) + NSTAGES - 1;                              \
            const int off = nc * CHUNK_FLOATS + tid * 4;                    \
            cp16(dA[nc & (NSTAGES - 1)], A + off);                          \
            cp16(dB[nc & (NSTAGES - 1)], B + off);                          \
            cp_commit();                                                    \
        }                                                                   \
        cp_wait<WAITN>();                                                   \
        const int s = (c) & (NSTAGES - 1);                                  \
        const float4 x = *reinterpret_cast<const float4*>(&buf[s][tid * 4]);\
        const float4 y = *reinterpret_cast<const float4*>(                  \
            &buf[s][CHUNK_FLOATS + tid * 4]);                               \
        acc0 += smoothl1(x.x, y.x);                                         \
        acc1 += smoothl1(x.y, y.y);                                         \
        acc0 += smoothl1(x.z, y.z);                                         \
        acc1 += smoothl1(x.w, y.w);                                         \
    }

    STEP(0, 3)
    STEP(1, 3)
    STEP(2, 3)
    STEP(3, 3)
    STEP(4, 3)
    STEP(5, 2)
    STEP(6, 1)
    STEP(7, 0)
#undef STEP

    float acc = acc0 + acc1;

    // block reduce (single barrier in the kernel)
    #pragma unroll
    for (int off = 16; off > 0; off >>= 1)
        acc += __shfl_xor_sync(0xFFFFFFFFu, acc, off);

    if (lid == 0) warp_sums[wid] = acc;
    __syncthreads();

    if (tid == 0) {
        float v = 0.0f;
        #pragma unroll
        for (int w = 0; w < BDIM / 32; ++w) v += warp_sums[w];
        // fire-and-forget reduction into the scalar output (REDG.F32)
        atomicAdd(out, v * ((float)m / (float)DCOLS));
    }
}

extern "C" void kernel_launch(void* const* d_in, const int* in_sizes, int n_in,
                              void* d_out, int out_size) {
    const float* inputs  = (const float*)d_in[0];
    const float* targets = (const float*)d_in[1];
    const int*   mask    = (const int*)d_in[2];
    float* out = (float*)d_out;

    zero_out_kernel<<<1, 1>>>(out);
    mask_smoothl1_cpasync4_kernel<<<NROWS, BDIM>>>(inputs, targets, mask, out);
}